// round 9
// baseline (speedup 1.0000x reference)
#include <cuda_runtime.h>
#include <cuda_bf16.h>
#include <cuda_fp16.h>
#include <math.h>
#include <stdint.h>

#define T_   4096
#define D_   2048
#define H_   16
#define HD_  128
#define TD3  6144   // 3*D

// ---------------- scratch (no allocations allowed) ----------------
__device__ float g_qkv[(size_t)T_ * TD3];   // [q | k | v] per row, fp32

// split-precision bf16 buffers for dense GEMMs
__device__ __nv_bfloat16 g_xh[(size_t)T_ * D_];
__device__ __nv_bfloat16 g_xl[(size_t)T_ * D_];
__device__ __nv_bfloat16 g_wqh[(size_t)TD3 * D_];   // Wqkv^T  [6144][2048]
__device__ __nv_bfloat16 g_wql[(size_t)TD3 * D_];
__device__ __nv_bfloat16 g_woh[(size_t)D_ * D_];    // Wout^T  [2048][2048]
__device__ __nv_bfloat16 g_wol[(size_t)D_ * D_];
__device__ __nv_bfloat16 g_aoh[(size_t)T_ * D_];
__device__ __nv_bfloat16 g_aol[(size_t)T_ * D_];

// attention fp16 operands
__device__ __half g_qfh[(size_t)T_ * D_];          // normalized q*scale*log2e, fp16
__device__ __half g_kfh[(size_t)T_ * D_];          // normalized k, fp16
__device__ __half g_vft[(size_t)H_ * HD_ * T_];    // V^T per head, fp16
__device__ __half g_maskh[(size_t)T_ * T_];        // mask * log2e, fp16

// =================================================================
// PTX helpers (portable: ldmatrix / mma.sync / cp.async)
// =================================================================
__device__ __forceinline__ uint32_t smem_u32(const void* p) {
    uint32_t a;
    asm("{ .reg .u64 t; cvta.to.shared.u64 t, %1; cvt.u32.u64 %0, t; }"
        : "=r"(a) : "l"(p));
    return a;
}
__device__ __forceinline__ void ldsm4(uint32_t* r, uint32_t a) {
    asm volatile("ldmatrix.sync.aligned.m8n8.x4.shared.b16 {%0,%1,%2,%3}, [%4];"
                 : "=r"(r[0]), "=r"(r[1]), "=r"(r[2]), "=r"(r[3]) : "r"(a));
}
__device__ __forceinline__ void mma16816(float* c, const uint32_t* a,
                                         uint32_t b0, uint32_t b1) {
    asm volatile(
        "mma.sync.aligned.m16n8k16.row.col.f32.bf16.bf16.f32 "
        "{%0,%1,%2,%3}, {%4,%5,%6,%7}, {%8,%9}, {%0,%1,%2,%3};"
        : "+f"(c[0]), "+f"(c[1]), "+f"(c[2]), "+f"(c[3])
        : "r"(a[0]), "r"(a[1]), "r"(a[2]), "r"(a[3]), "r"(b0), "r"(b1));
}
__device__ __forceinline__ void mma16816h(float* c, const uint32_t* a,
                                          uint32_t b0, uint32_t b1) {
    asm volatile(
        "mma.sync.aligned.m16n8k16.row.col.f32.f16.f16.f32 "
        "{%0,%1,%2,%3}, {%4,%5,%6,%7}, {%8,%9}, {%0,%1,%2,%3};"
        : "+f"(c[0]), "+f"(c[1]), "+f"(c[2]), "+f"(c[3])
        : "r"(a[0]), "r"(a[1]), "r"(a[2]), "r"(a[3]), "r"(b0), "r"(b1));
}
__device__ __forceinline__ uint32_t ex2h2(uint32_t x) {
    uint32_t r;
    asm("ex2.approx.f16x2 %0, %1;" : "=r"(r) : "r"(x));
    return r;
}
#define CP_ASYNC16(sa, ga) \
    asm volatile("cp.async.cg.shared.global [%0], [%1], 16;" :: "r"(sa), "l"(ga))
#define CP_COMMIT() asm volatile("cp.async.commit_group;" ::: "memory")
#define CP_WAIT0()  asm volatile("cp.async.wait_group 0;" ::: "memory")

#define LOG2E 1.4426950408889634f

// =================================================================
// Split / transpose / convert kernels
// =================================================================
__global__ __launch_bounds__(256) void split_hl(const float4* __restrict__ src,
                                                uint2* __restrict__ hi,
                                                uint2* __restrict__ lo)
{
    size_t i = (size_t)blockIdx.x * 256 + threadIdx.x;
    float4 v = src[i];
    __nv_bfloat162 h0 = __floats2bfloat162_rn(v.x, v.y);
    __nv_bfloat162 h1 = __floats2bfloat162_rn(v.z, v.w);
    float rx = v.x - __low2float(h0),  ry = v.y - __high2float(h0);
    float rz = v.z - __low2float(h1),  rw = v.w - __high2float(h1);
    __nv_bfloat162 l0 = __floats2bfloat162_rn(rx, ry);
    __nv_bfloat162 l1 = __floats2bfloat162_rn(rz, rw);
    uint2 hv, lv;
    hv.x = *reinterpret_cast<unsigned*>(&h0); hv.y = *reinterpret_cast<unsigned*>(&h1);
    lv.x = *reinterpret_cast<unsigned*>(&l0); lv.y = *reinterpret_cast<unsigned*>(&l1);
    hi[i] = hv;
    lo[i] = lv;
}

// mask * log2e -> fp16 (prepared for base-2 exp; -inf -> fp16 -inf -> P=0)
__global__ __launch_bounds__(256) void mask2bf(const float4* __restrict__ m)
{
    size_t i = (size_t)blockIdx.x * 256 + threadIdx.x;
    float4 v = m[i];
    __half2 a = __floats2half2_rn(v.x * LOG2E, v.y * LOG2E);
    __half2 b = __floats2half2_rn(v.z * LOG2E, v.w * LOG2E);
    uint2 o;
    o.x = *reinterpret_cast<unsigned*>(&a);
    o.y = *reinterpret_cast<unsigned*>(&b);
    ((uint2*)g_maskh)[i] = o;
}

// src[R][C] fp32  ->  out[C][R] bf16 hi/lo (transpose + split)
__global__ __launch_bounds__(256) void tsplit(const float* __restrict__ src,
                                              __nv_bfloat16* __restrict__ dh,
                                              __nv_bfloat16* __restrict__ dl,
                                              int R, int C)
{
    __shared__ float tile[32][33];
    int tx = threadIdx.x, ty = threadIdx.y;
    int x0 = blockIdx.x * 32, y0 = blockIdx.y * 32;
    #pragma unroll
    for (int j = 0; j < 4; j++)
        tile[ty + j * 8][tx] = src[(size_t)(y0 + ty + j * 8) * C + x0 + tx];
    __syncthreads();
    #pragma unroll
    for (int j = 0; j < 4; j++) {
        float v = tile[tx][ty + j * 8];
        __nv_bfloat16 h = __float2bfloat16(v);
        __nv_bfloat16 l = __float2bfloat16(v - __bfloat162float(h));
        size_t o = (size_t)(x0 + ty + j * 8) * R + y0 + tx;
        dh[o] = h;
        dl[o] = l;
    }
}

// V region of g_qkv -> per-head transposed fp16: g_vft[h][d][t]
__global__ __launch_bounds__(256) void vtsplit()
{
    __shared__ float tile[32][33];
    int tx = threadIdx.x, ty = threadIdx.y;
    int t0 = blockIdx.x * 32, d0 = blockIdx.y * 32, h = blockIdx.z;
    #pragma unroll
    for (int j = 0; j < 4; j++)
        tile[ty + j * 8][tx] =
            g_qkv[(size_t)(t0 + ty + j * 8) * TD3 + 2 * D_ + h * HD_ + d0 + tx];
    __syncthreads();
    size_t base = (size_t)h * HD_ * T_;
    #pragma unroll
    for (int j = 0; j < 4; j++) {
        float v = tile[tx][ty + j * 8];
        size_t o = base + (size_t)(d0 + ty + j * 8) * T_ + t0 + tx;
        g_vft[o] = __float2half(v);
    }
}

// =================================================================
// Split-bf16 mma.sync GEMM (unchanged — passing, tensor=52.8%)
// =================================================================
#define BM 128
#define BN 128
#define BKC 32
#define ROWB 80
#define TILE_B (128 * ROWB)
#define STAGE_B (4 * TILE_B)
#define GEMM_SMEM (2 * STAGE_B)

__device__ __forceinline__ void cpa_tile(uint32_t sbase,
                                         const __nv_bfloat16* __restrict__ g,
                                         int row0, int k0, int K, int tid)
{
    #pragma unroll
    for (int i = 0; i < 2; i++) {
        int ch = tid + i * 256;
        int r  = ch >> 2;
        int cc = (ch & 3) * 8;
        uint32_t sa = sbase + r * ROWB + cc * 2;
        const void* ga = g + (size_t)(row0 + r) * K + k0 + cc;
        CP_ASYNC16(sa, ga);
    }
}

__global__ __launch_bounds__(256) void gemm_split(
    const __nv_bfloat16* __restrict__ Ah, const __nv_bfloat16* __restrict__ Al,
    const __nv_bfloat16* __restrict__ Bh, const __nv_bfloat16* __restrict__ Bl,
    float* __restrict__ C, int M, int N, int K)
{
    extern __shared__ char smem[];
    uint32_t sb = smem_u32(smem);
    const int tid  = threadIdx.x;
    const int lane = tid & 31;
    const int wid  = tid >> 5;
    const int wm   = wid >> 2;
    const int wn   = wid & 3;
    const int m0 = blockIdx.y * BM;
    const int n0 = blockIdx.x * BN;
    const int NC = K / BKC;

    float acc[4][4][4] = {};

    cpa_tile(sb,              Ah, m0, 0, K, tid);
    cpa_tile(sb + TILE_B,     Al, m0, 0, K, tid);
    cpa_tile(sb + 2 * TILE_B, Bh, n0, 0, K, tid);
    cpa_tile(sb + 3 * TILE_B, Bl, n0, 0, K, tid);
    CP_COMMIT();
    CP_WAIT0();
    __syncthreads();

    const int lm  = lane & 15;
    const int lk8 = (lane >> 4) * 8;

    for (int c = 0; c < NC; c++) {
        uint32_t sbuf = sb + (c & 1) * STAGE_B;
        if (c + 1 < NC) {
            uint32_t snext = sb + ((c + 1) & 1) * STAGE_B;
            int k0 = (c + 1) * BKC;
            cpa_tile(snext,              Ah, m0, k0, K, tid);
            cpa_tile(snext + TILE_B,     Al, m0, k0, K, tid);
            cpa_tile(snext + 2 * TILE_B, Bh, n0, k0, K, tid);
            cpa_tile(snext + 3 * TILE_B, Bl, n0, k0, K, tid);
            CP_COMMIT();
        }

        uint32_t sA  = sbuf;
        uint32_t sAl = sbuf + TILE_B;
        uint32_t sB  = sbuf + 2 * TILE_B;
        uint32_t sBl = sbuf + 3 * TILE_B;

        #pragma unroll
        for (int ks = 0; ks < 2; ks++) {
            uint32_t kb = (ks * 16 + lk8) * 2;
            uint32_t ah[4][4], al[4][4], bh[2][4], bl[2][4];
            #pragma unroll
            for (int mf = 0; mf < 4; mf++) {
                uint32_t ro = (wm * 64 + mf * 16 + lm) * ROWB + kb;
                ldsm4(ah[mf], sA + ro);
                ldsm4(al[mf], sAl + ro);
            }
            #pragma unroll
            for (int nf2 = 0; nf2 < 2; nf2++) {
                uint32_t ro = (wn * 32 + nf2 * 16 + lm) * ROWB + kb;
                ldsm4(bh[nf2], sB + ro);
                ldsm4(bl[nf2], sBl + ro);
            }
            #pragma unroll
            for (int mf = 0; mf < 4; mf++)
                #pragma unroll
                for (int nf = 0; nf < 4; nf++) {
                    uint32_t b0h = bh[nf >> 1][nf & 1];
                    uint32_t b1h = bh[nf >> 1][(nf & 1) + 2];
                    uint32_t b0l = bl[nf >> 1][nf & 1];
                    uint32_t b1l = bl[nf >> 1][(nf & 1) + 2];
                    mma16816(acc[mf][nf], ah[mf], b0h, b1h);
                    mma16816(acc[mf][nf], ah[mf], b0l, b1l);
                    mma16816(acc[mf][nf], al[mf], b0h, b1h);
                }
        }

        if (c + 1 < NC) {
            CP_WAIT0();
            __syncthreads();
        }
    }

    int mbase = m0 + wm * 64;
    int nbase = n0 + wn * 32;
    #pragma unroll
    for (int mf = 0; mf < 4; mf++)
        #pragma unroll
        for (int nf = 0; nf < 4; nf++) {
            int r0 = mbase + mf * 16 + (lane >> 2);
            int c0 = nbase + nf * 8 + (lane & 3) * 2;
            *(float2*)&C[(size_t)r0 * N + c0] =
                make_float2(acc[mf][nf][0], acc[mf][nf][1]);
            *(float2*)&C[(size_t)(r0 + 8) * N + c0] =
                make_float2(acc[mf][nf][2], acc[mf][nf][3]);
        }
}

// =================================================================
// L2-normalize q,k -> fp16 (softmax scale * log2e folded into q).
// =================================================================
__global__ __launch_bounds__(256) void l2norm_qk()
{
    int gw = blockIdx.x * 8 + (threadIdx.x >> 5);
    int l  = threadIdx.x & 31;
    int which = gw >> 16;           // 0 = q, 1 = k
    int rem   = gw & 65535;
    int t = rem >> 4;
    int h = rem & 15;

    const float* p = g_qkv + (size_t)t * TD3 + which * D_ + h * HD_ + l * 4;
    float4 v = *(const float4*)p;
    float ss = v.x * v.x + v.y * v.y + v.z * v.z + v.w * v.w;
    #pragma unroll
    for (int o = 16; o; o >>= 1) ss += __shfl_xor_sync(0xffffffffu, ss, o);
    // q: fold 128^-0.5 * log2(e) so S accumulators are base-2 exponents
    float sc = which ? 1.0f : (0.08838834764831845f * LOG2E);
    float inv = sc / fmaxf(sqrtf(ss), 1e-12f);
    __half2 h0 = __floats2half2_rn(v.x * inv, v.y * inv);
    __half2 h1 = __floats2half2_rn(v.z * inv, v.w * inv);
    uint2 hv;
    hv.x = *reinterpret_cast<unsigned*>(&h0);
    hv.y = *reinterpret_cast<unsigned*>(&h1);
    __half* dst = which ? g_kfh : g_qfh;
    *(uint2*)(dst + (size_t)t * D_ + h * HD_ + l * 4) = hv;
}

// =================================================================
// Tensor-core flash attention, fp16, no-max softmax, ex2.f16x2,
// ones-MMA row sums. K AND V double-buffered -> ONE barrier per tile.
// grid (H, T/128), 256 thr (8 warps), warp w owns q-rows 16w..16w+15.
// smem: Q 32KB, K 2x16KB, V 2x16KB = 96KB -> 2 CTAs/SM.
// =================================================================
#define AQ_OFF2 0
#define AK2(s)  (32768 + (s) * 16384)
#define AV2(s)  (65536 + (s) * 16384)
#define ATTN2_SMEM 98304
#define NT_ (T_ / 64)

__global__ __launch_bounds__(256, 2) void attn2()
{
    extern __shared__ char sm2[];
    uint32_t sb = smem_u32(sm2);
    const int tid = threadIdx.x, lane = tid & 31, w = tid >> 5;
    const int g = lane >> 2, q4 = lane & 3;
    const int lm = lane & 15, lhi = lane >> 4;
    const int h = blockIdx.x, q0 = blockIdx.y * 128;
    const uint32_t ONES2 = 0x3C003C00u;   // half2(1,1)

    const size_t vbase = (size_t)h * HD_ * T_;

    // ---- prologue: Q + K(0) + V(0) ----
    #pragma unroll
    for (int i = 0; i < 8; i++) {
        int ch = tid + i * 256;
        int r = ch >> 4, c = ch & 15;
        CP_ASYNC16(sb + AQ_OFF2 + r * 256 + ((c ^ (r & 7)) << 4),
                   g_qfh + (size_t)(q0 + r) * D_ + h * HD_ + c * 8);
    }
    #pragma unroll
    for (int i = 0; i < 4; i++) {
        int ch = tid + i * 256;
        int r = ch >> 4, c = ch & 15;
        CP_ASYNC16(sb + AK2(0) + r * 256 + ((c ^ (r & 7)) << 4),
                   g_kfh + (size_t)r * D_ + h * HD_ + c * 8);
    }
    #pragma unroll
    for (int i = 0; i < 4; i++) {
        int ch = tid + i * 256;
        int r = ch >> 3, c = ch & 7;
        uint32_t so = r * 128 + ((c ^ (r & 7)) << 4);
        CP_ASYNC16(sb + AV2(0) + so, g_vft + vbase + (size_t)r * T_ + c * 8);
    }
    CP_COMMIT();

    float o[16][4] = {};
    float lsum[4] = {};     // [0]: row sum (row0), [2]: row sum (row0+8)
    const int row0 = q0 + w * 16 + g;

    CP_WAIT0();
    __syncthreads();

    for (int ti = 0; ti < NT_; ti++) {
        const int kt = ti * 64;

        // ---- issue K(ti+1), V(ti+1) FIRST (targets stage last read
        //      in tile ti-1, protected by the end-of-(ti-1) barrier) ----
        if (ti + 1 < NT_) {
            const int kn = kt + 64;
            const int sn = (ti + 1) & 1;
            #pragma unroll
            for (int i = 0; i < 4; i++) {
                int ch = tid + i * 256;
                int r = ch >> 4, c = ch & 15;
                CP_ASYNC16(sb + AK2(sn) + r * 256 + ((c ^ (r & 7)) << 4),
                           g_kfh + (size_t)(kn + r) * D_ + h * HD_ + c * 8);
            }
            #pragma unroll
            for (int i = 0; i < 4; i++) {
                int ch = tid + i * 256;
                int r = ch >> 3, c = ch & 7;
                uint32_t so = r * 128 + ((c ^ (r & 7)) << 4);
                CP_ASYNC16(sb + AV2(sn) + so,
                           g_vft + vbase + (size_t)r * T_ + kn + c * 8);
            }
            CP_COMMIT();
        }

        // ---- mask prefetch (fp16x2, pre-scaled by log2e) ----
        uint32_t mfr[16];
        {
            const __half* mb0 = g_maskh + (size_t)row0 * T_ + kt + q4 * 2;
            #pragma unroll
            for (int nf = 0; nf < 8; nf++) {
                mfr[nf]     = *(const uint32_t*)(mb0 + nf * 8);
                mfr[8 + nf] = *(const uint32_t*)(mb0 + 8 * T_ + nf * 8);
            }
        }

        // ---- S = Q K^T (scale*log2e pre-folded into q), fp16 ----
        const uint32_t k_base = sb + AK2(ti & 1);
        float s[8][4] = {};
        #pragma unroll
        for (int ks = 0; ks < 8; ks++) {
            int cb = ks * 2 + lhi;
            uint32_t aq[4];
            {
                int r = w * 16 + lm;
                ldsm4(aq, sb + AQ_OFF2 + r * 256 + ((cb ^ (r & 7)) << 4));
            }
            #pragma unroll
            for (int n2 = 0; n2 < 4; n2++) {
                uint32_t kf[4];
                int r = n2 * 16 + lm;
                ldsm4(kf, k_base + r * 256 + ((cb ^ (r & 7)) << 4));
                mma16816h(s[2 * n2],     aq, kf[0], kf[2]);
                mma16816h(s[2 * n2 + 1], aq, kf[1], kf[3]);
            }
        }

        // ---- P = 2^(S + mask) via half2 HADD2 + ex2; sums; O += P V ----
        const uint32_t v_base = sb + AV2(ti & 1);
        #pragma unroll
        for (int j = 0; j < 4; j++) {
            uint32_t ph[4];
            #pragma unroll
            for (int u = 0; u < 2; u++) {
                int idx = 2 * j + u;
                __half2 hab = __floats2half2_rn(s[idx][0], s[idx][1]);
                __half2 hcd = __floats2half2_rn(s[idx][2], s[idx][3]);
                hab = __hadd2(hab, *reinterpret_cast<__half2*>(&mfr[idx]));
                hcd = __hadd2(hcd, *reinterpret_cast<__half2*>(&mfr[8 + idx]));
                ph[2 * u]     = ex2h2(*reinterpret_cast<unsigned*>(&hab));
                ph[2 * u + 1] = ex2h2(*reinterpret_cast<unsigned*>(&hcd));
            }
            // row sums: P (16x16) x ones(16x8) accumulated into lsum
            mma16816h(lsum, ph, ONES2, ONES2);

            int cb = j * 2 + lhi;
            #pragma unroll
            for (int n2 = 0; n2 < 8; n2++) {
                uint32_t vh[4];
                int r = n2 * 16 + lm;
                ldsm4(vh, v_base + r * 128 + ((cb ^ (r & 7)) << 4));
                mma16816h(o[2 * n2],     ph, vh[0], vh[2]);
                mma16816h(o[2 * n2 + 1], ph, vh[1], vh[3]);
            }
        }

        // ---- single barrier per tile: next-stage data ready + consumed ----
        if (ti + 1 < NT_) {
            CP_WAIT0();
            __syncthreads();
        }
    }

    // ---- epilogue: normalize by ones-MMA row sums + bf16 hi/lo split ----
    float inv0 = 1.f / lsum[0], inv1 = 1.f / lsum[2];
    size_t base0 = (size_t)row0 * D_ + h * HD_ + q4 * 2;
    size_t base1 = base0 + (size_t)8 * D_;
    #pragma unroll
    for (int nf = 0; nf < 16; nf++) {
        float a = o[nf][0] * inv0, b = o[nf][1] * inv0;
        __nv_bfloat162 hb = __floats2bfloat162_rn(a, b);
        __nv_bfloat162 lb = __floats2bfloat162_rn(
            a - __low2float(hb), b - __high2float(hb));
        *(uint32_t*)(g_aoh + base0 + nf * 8) = *reinterpret_cast<unsigned*>(&hb);
        *(uint32_t*)(g_aol + base0 + nf * 8) = *reinterpret_cast<unsigned*>(&lb);
        float cme = o[nf][2] * inv1, d = o[nf][3] * inv1;
        __nv_bfloat162 hb1 = __floats2bfloat162_rn(cme, d);
        __nv_bfloat162 lb1 = __floats2bfloat162_rn(
            cme - __low2float(hb1), d - __high2float(hb1));
        *(uint32_t*)(g_aoh + base1 + nf * 8) = *reinterpret_cast<unsigned*>(&hb1);
        *(uint32_t*)(g_aol + base1 + nf * 8) = *reinterpret_cast<unsigned*>(&lb1);
    }
}

// =================================================================
// Launch
// =================================================================
extern "C" void kernel_launch(void* const* d_in, const int* in_sizes, int n_in,
                              void* d_out, int out_size)
{
    const float* x    = (const float*)d_in[0];
    const float* mask = (const float*)d_in[1];
    const float* Wqkv = (const float*)d_in[2];
    const float* Wout = (const float*)d_in[3];
    float* out = (float*)d_out;

    float* qkv;
    __nv_bfloat16 *xh, *xl, *wqh, *wql, *woh, *wol, *aoh, *aol;
    cudaGetSymbolAddress((void**)&qkv, g_qkv);
    cudaGetSymbolAddress((void**)&xh,  g_xh);
    cudaGetSymbolAddress((void**)&xl,  g_xl);
    cudaGetSymbolAddress((void**)&wqh, g_wqh);
    cudaGetSymbolAddress((void**)&wql, g_wql);
    cudaGetSymbolAddress((void**)&woh, g_woh);
    cudaGetSymbolAddress((void**)&wol, g_wol);
    cudaGetSymbolAddress((void**)&aoh, g_aoh);
    cudaGetSymbolAddress((void**)&aol, g_aol);

    cudaFuncSetAttribute(gemm_split,
                         cudaFuncAttributeMaxDynamicSharedMemorySize, GEMM_SMEM);
    cudaFuncSetAttribute(attn2,
                         cudaFuncAttributeMaxDynamicSharedMemorySize, ATTN2_SMEM);

    // 1) split x / weights; mask*log2e -> fp16
    split_hl<<<(T_ * D_ / 4) / 256, 256>>>((const float4*)x, (uint2*)xh, (uint2*)xl);
    tsplit<<<dim3(TD3 / 32, D_ / 32), dim3(32, 8)>>>(Wqkv, wqh, wql, D_, TD3);
    tsplit<<<dim3(D_ / 32,  D_ / 32), dim3(32, 8)>>>(Wout, woh, wol, D_, D_);
    mask2bf<<<(T_ * (size_t)T_ / 4) / 256, 256>>>((const float4*)mask);

    // 2) qkv = x @ W_qkv
    gemm_split<<<dim3(TD3 / BN, T_ / BM), 256, GEMM_SMEM>>>(
        xh, xl, wqh, wql, qkv, T_, TD3, D_);

    // 3) normalize q (scale*log2e folded), k -> fp16; transpose V -> fp16
    l2norm_qk<<<(T_ * H_ * 2) / 8, 256>>>();
    vtsplit<<<dim3(T_ / 32, HD_ / 32, H_), dim3(32, 8)>>>();

    // 4) fp16 flash attention (1 barrier/tile, K+V double-buffered)
    attn2<<<dim3(H_, T_ / 128), 256, ATTN2_SMEM>>>();

    // 5) out = ao @ W_out
    gemm_split<<<dim3(D_ / BN, T_ / BM), 256, GEMM_SMEM>>>(
        aoh, aol, woh, wol, out, T_, D_, D_);
}

// round 12
// speedup vs baseline: 1.0417x; 1.0417x over previous
#include <cuda_runtime.h>
#include <cuda_bf16.h>
#include <cuda_fp16.h>
#include <math.h>
#include <stdint.h>

#define T_   4096
#define D_   2048
#define H_   16
#define HD_  128
#define TD3  6144   // 3*D

// ---------------- scratch (no allocations allowed) ----------------
__device__ float g_qkv[(size_t)T_ * TD3];   // [q | k | v] per row, fp32

// split-precision bf16 buffers for dense GEMMs
__device__ __nv_bfloat16 g_xh[(size_t)T_ * D_];
__device__ __nv_bfloat16 g_xl[(size_t)T_ * D_];
__device__ __nv_bfloat16 g_wqh[(size_t)TD3 * D_];   // Wqkv^T  [6144][2048]
__device__ __nv_bfloat16 g_wql[(size_t)TD3 * D_];
__device__ __nv_bfloat16 g_woh[(size_t)D_ * D_];    // Wout^T  [2048][2048]
__device__ __nv_bfloat16 g_wol[(size_t)D_ * D_];
__device__ __nv_bfloat16 g_aoh[(size_t)T_ * D_];
__device__ __nv_bfloat16 g_aol[(size_t)T_ * D_];

// attention fp16 operands
__device__ __half g_qfh[(size_t)T_ * D_];          // normalized q*scale*log2e, fp16
__device__ __half g_kfh[(size_t)T_ * D_];          // normalized k, fp16
__device__ __half g_vft[(size_t)H_ * HD_ * T_];    // V^T per head, fp16
__device__ __half g_maskh[(size_t)T_ * T_];        // mask * log2e, fp16

// =================================================================
// PTX helpers (portable: ldmatrix / mma.sync / cp.async)
// =================================================================
__device__ __forceinline__ uint32_t smem_u32(const void* p) {
    uint32_t a;
    asm("{ .reg .u64 t; cvta.to.shared.u64 t, %1; cvt.u32.u64 %0, t; }"
        : "=r"(a) : "l"(p));
    return a;
}
__device__ __forceinline__ void ldsm4(uint32_t* r, uint32_t a) {
    asm volatile("ldmatrix.sync.aligned.m8n8.x4.shared.b16 {%0,%1,%2,%3}, [%4];"
                 : "=r"(r[0]), "=r"(r[1]), "=r"(r[2]), "=r"(r[3]) : "r"(a));
}
__device__ __forceinline__ void mma16816(float* c, const uint32_t* a,
                                         uint32_t b0, uint32_t b1) {
    asm volatile(
        "mma.sync.aligned.m16n8k16.row.col.f32.bf16.bf16.f32 "
        "{%0,%1,%2,%3}, {%4,%5,%6,%7}, {%8,%9}, {%0,%1,%2,%3};"
        : "+f"(c[0]), "+f"(c[1]), "+f"(c[2]), "+f"(c[3])
        : "r"(a[0]), "r"(a[1]), "r"(a[2]), "r"(a[3]), "r"(b0), "r"(b1));
}
__device__ __forceinline__ void mma16816h(float* c, const uint32_t* a,
                                          uint32_t b0, uint32_t b1) {
    asm volatile(
        "mma.sync.aligned.m16n8k16.row.col.f32.f16.f16.f32 "
        "{%0,%1,%2,%3}, {%4,%5,%6,%7}, {%8,%9}, {%0,%1,%2,%3};"
        : "+f"(c[0]), "+f"(c[1]), "+f"(c[2]), "+f"(c[3])
        : "r"(a[0]), "r"(a[1]), "r"(a[2]), "r"(a[3]), "r"(b0), "r"(b1));
}
__device__ __forceinline__ uint32_t ex2h2(uint32_t x) {
    uint32_t r;
    asm("ex2.approx.f16x2 %0, %1;" : "=r"(r) : "r"(x));
    return r;
}
#define CP_ASYNC16(sa, ga) \
    asm volatile("cp.async.cg.shared.global [%0], [%1], 16;" :: "r"(sa), "l"(ga))
#define CP_COMMIT() asm volatile("cp.async.commit_group;" ::: "memory")
#define CP_WAIT0()  asm volatile("cp.async.wait_group 0;" ::: "memory")

#define LOG2E 1.4426950408889634f

// =================================================================
// Split / transpose / convert kernels
// =================================================================
__global__ __launch_bounds__(256) void split_hl(const float4* __restrict__ src,
                                                uint2* __restrict__ hi,
                                                uint2* __restrict__ lo)
{
    size_t i = (size_t)blockIdx.x * 256 + threadIdx.x;
    float4 v = src[i];
    __nv_bfloat162 h0 = __floats2bfloat162_rn(v.x, v.y);
    __nv_bfloat162 h1 = __floats2bfloat162_rn(v.z, v.w);
    float rx = v.x - __low2float(h0),  ry = v.y - __high2float(h0);
    float rz = v.z - __low2float(h1),  rw = v.w - __high2float(h1);
    __nv_bfloat162 l0 = __floats2bfloat162_rn(rx, ry);
    __nv_bfloat162 l1 = __floats2bfloat162_rn(rz, rw);
    uint2 hv, lv;
    hv.x = *reinterpret_cast<unsigned*>(&h0); hv.y = *reinterpret_cast<unsigned*>(&h1);
    lv.x = *reinterpret_cast<unsigned*>(&l0); lv.y = *reinterpret_cast<unsigned*>(&l1);
    hi[i] = hv;
    lo[i] = lv;
}

// mask * log2e -> fp16 (prepared for base-2 exp; -inf -> fp16 -inf -> P=0)
__global__ __launch_bounds__(256) void mask2bf(const float4* __restrict__ m)
{
    size_t i = (size_t)blockIdx.x * 256 + threadIdx.x;
    float4 v = m[i];
    __half2 a = __floats2half2_rn(v.x * LOG2E, v.y * LOG2E);
    __half2 b = __floats2half2_rn(v.z * LOG2E, v.w * LOG2E);
    uint2 o;
    o.x = *reinterpret_cast<unsigned*>(&a);
    o.y = *reinterpret_cast<unsigned*>(&b);
    ((uint2*)g_maskh)[i] = o;
}

// src[R][C] fp32  ->  out[C][R] bf16 hi/lo (transpose + split)
__global__ __launch_bounds__(256) void tsplit(const float* __restrict__ src,
                                              __nv_bfloat16* __restrict__ dh,
                                              __nv_bfloat16* __restrict__ dl,
                                              int R, int C)
{
    __shared__ float tile[32][33];
    int tx = threadIdx.x, ty = threadIdx.y;
    int x0 = blockIdx.x * 32, y0 = blockIdx.y * 32;
    #pragma unroll
    for (int j = 0; j < 4; j++)
        tile[ty + j * 8][tx] = src[(size_t)(y0 + ty + j * 8) * C + x0 + tx];
    __syncthreads();
    #pragma unroll
    for (int j = 0; j < 4; j++) {
        float v = tile[tx][ty + j * 8];
        __nv_bfloat16 h = __float2bfloat16(v);
        __nv_bfloat16 l = __float2bfloat16(v - __bfloat162float(h));
        size_t o = (size_t)(x0 + ty + j * 8) * R + y0 + tx;
        dh[o] = h;
        dl[o] = l;
    }
}

// V region of g_qkv -> per-head transposed fp16: g_vft[h][d][t]
__global__ __launch_bounds__(256) void vtsplit()
{
    __shared__ float tile[32][33];
    int tx = threadIdx.x, ty = threadIdx.y;
    int t0 = blockIdx.x * 32, d0 = blockIdx.y * 32, h = blockIdx.z;
    #pragma unroll
    for (int j = 0; j < 4; j++)
        tile[ty + j * 8][tx] =
            g_qkv[(size_t)(t0 + ty + j * 8) * TD3 + 2 * D_ + h * HD_ + d0 + tx];
    __syncthreads();
    size_t base = (size_t)h * HD_ * T_;
    #pragma unroll
    for (int j = 0; j < 4; j++) {
        float v = tile[tx][ty + j * 8];
        size_t o = base + (size_t)(d0 + ty + j * 8) * T_ + t0 + tx;
        g_vft[o] = __float2half(v);
    }
}

// =================================================================
// Split-bf16 mma.sync GEMM (unchanged — passing, tensor=52.8%)
// =================================================================
#define BM 128
#define BN 128
#define BKC 32
#define ROWB 80
#define TILE_B (128 * ROWB)
#define STAGE_B (4 * TILE_B)
#define GEMM_SMEM (2 * STAGE_B)

__device__ __forceinline__ void cpa_tile(uint32_t sbase,
                                         const __nv_bfloat16* __restrict__ g,
                                         int row0, int k0, int K, int tid)
{
    #pragma unroll
    for (int i = 0; i < 2; i++) {
        int ch = tid + i * 256;
        int r  = ch >> 2;
        int cc = (ch & 3) * 8;
        uint32_t sa = sbase + r * ROWB + cc * 2;
        const void* ga = g + (size_t)(row0 + r) * K + k0 + cc;
        CP_ASYNC16(sa, ga);
    }
}

__global__ __launch_bounds__(256) void gemm_split(
    const __nv_bfloat16* __restrict__ Ah, const __nv_bfloat16* __restrict__ Al,
    const __nv_bfloat16* __restrict__ Bh, const __nv_bfloat16* __restrict__ Bl,
    float* __restrict__ C, int M, int N, int K)
{
    extern __shared__ char smem[];
    uint32_t sb = smem_u32(smem);
    const int tid  = threadIdx.x;
    const int lane = tid & 31;
    const int wid  = tid >> 5;
    const int wm   = wid >> 2;
    const int wn   = wid & 3;
    const int m0 = blockIdx.y * BM;
    const int n0 = blockIdx.x * BN;
    const int NC = K / BKC;

    float acc[4][4][4] = {};

    cpa_tile(sb,              Ah, m0, 0, K, tid);
    cpa_tile(sb + TILE_B,     Al, m0, 0, K, tid);
    cpa_tile(sb + 2 * TILE_B, Bh, n0, 0, K, tid);
    cpa_tile(sb + 3 * TILE_B, Bl, n0, 0, K, tid);
    CP_COMMIT();
    CP_WAIT0();
    __syncthreads();

    const int lm  = lane & 15;
    const int lk8 = (lane >> 4) * 8;

    for (int c = 0; c < NC; c++) {
        uint32_t sbuf = sb + (c & 1) * STAGE_B;
        if (c + 1 < NC) {
            uint32_t snext = sb + ((c + 1) & 1) * STAGE_B;
            int k0 = (c + 1) * BKC;
            cpa_tile(snext,              Ah, m0, k0, K, tid);
            cpa_tile(snext + TILE_B,     Al, m0, k0, K, tid);
            cpa_tile(snext + 2 * TILE_B, Bh, n0, k0, K, tid);
            cpa_tile(snext + 3 * TILE_B, Bl, n0, k0, K, tid);
            CP_COMMIT();
        }

        uint32_t sA  = sbuf;
        uint32_t sAl = sbuf + TILE_B;
        uint32_t sB  = sbuf + 2 * TILE_B;
        uint32_t sBl = sbuf + 3 * TILE_B;

        #pragma unroll
        for (int ks = 0; ks < 2; ks++) {
            uint32_t kb = (ks * 16 + lk8) * 2;
            uint32_t ah[4][4], al[4][4], bh[2][4], bl[2][4];
            #pragma unroll
            for (int mf = 0; mf < 4; mf++) {
                uint32_t ro = (wm * 64 + mf * 16 + lm) * ROWB + kb;
                ldsm4(ah[mf], sA + ro);
                ldsm4(al[mf], sAl + ro);
            }
            #pragma unroll
            for (int nf2 = 0; nf2 < 2; nf2++) {
                uint32_t ro = (wn * 32 + nf2 * 16 + lm) * ROWB + kb;
                ldsm4(bh[nf2], sB + ro);
                ldsm4(bl[nf2], sBl + ro);
            }
            #pragma unroll
            for (int mf = 0; mf < 4; mf++)
                #pragma unroll
                for (int nf = 0; nf < 4; nf++) {
                    uint32_t b0h = bh[nf >> 1][nf & 1];
                    uint32_t b1h = bh[nf >> 1][(nf & 1) + 2];
                    uint32_t b0l = bl[nf >> 1][nf & 1];
                    uint32_t b1l = bl[nf >> 1][(nf & 1) + 2];
                    mma16816(acc[mf][nf], ah[mf], b0h, b1h);
                    mma16816(acc[mf][nf], ah[mf], b0l, b1l);
                    mma16816(acc[mf][nf], al[mf], b0h, b1h);
                }
        }

        if (c + 1 < NC) {
            CP_WAIT0();
            __syncthreads();
        }
    }

    int mbase = m0 + wm * 64;
    int nbase = n0 + wn * 32;
    #pragma unroll
    for (int mf = 0; mf < 4; mf++)
        #pragma unroll
        for (int nf = 0; nf < 4; nf++) {
            int r0 = mbase + mf * 16 + (lane >> 2);
            int c0 = nbase + nf * 8 + (lane & 3) * 2;
            *(float2*)&C[(size_t)r0 * N + c0] =
                make_float2(acc[mf][nf][0], acc[mf][nf][1]);
            *(float2*)&C[(size_t)(r0 + 8) * N + c0] =
                make_float2(acc[mf][nf][2], acc[mf][nf][3]);
        }
}

// =================================================================
// L2-normalize q,k -> fp16 (softmax scale * log2e folded into q).
// =================================================================
__global__ __launch_bounds__(256) void l2norm_qk()
{
    int gw = blockIdx.x * 8 + (threadIdx.x >> 5);
    int l  = threadIdx.x & 31;
    int which = gw >> 16;           // 0 = q, 1 = k
    int rem   = gw & 65535;
    int t = rem >> 4;
    int h = rem & 15;

    const float* p = g_qkv + (size_t)t * TD3 + which * D_ + h * HD_ + l * 4;
    float4 v = *(const float4*)p;
    float ss = v.x * v.x + v.y * v.y + v.z * v.z + v.w * v.w;
    #pragma unroll
    for (int o = 16; o; o >>= 1) ss += __shfl_xor_sync(0xffffffffu, ss, o);
    // q: fold 128^-0.5 * log2(e) so S accumulators are base-2 exponents
    float sc = which ? 1.0f : (0.08838834764831845f * LOG2E);
    float inv = sc / fmaxf(sqrtf(ss), 1e-12f);
    __half2 h0 = __floats2half2_rn(v.x * inv, v.y * inv);
    __half2 h1 = __floats2half2_rn(v.z * inv, v.w * inv);
    uint2 hv;
    hv.x = *reinterpret_cast<unsigned*>(&h0);
    hv.y = *reinterpret_cast<unsigned*>(&h1);
    __half* dst = which ? g_kfh : g_qfh;
    *(uint2*)(dst + (size_t)t * D_ + h * HD_ + l * 4) = hv;
}

// =================================================================
// Tensor-core flash attention, fp16, no-max softmax, ex2.f16x2,
// ones-MMA row sums. K+V double-buffered, ONE barrier per tile.
// REGISTER DIET: 64-key tile processed as two 32-key halves,
// half-loop kept ROLLED (#pragma unroll 1) for small code footprint.
// grid (H, T/128), 256 thr (8 warps), warp w owns q-rows 16w..16w+15.
// smem: Q 32KB, K 2x16KB, V 2x16KB = 96KB -> 2 CTAs/SM.
// =================================================================
#define AQ_OFF2 0
#define AK2(s)  (32768 + (s) * 16384)
#define AV2(s)  (65536 + (s) * 16384)
#define ATTN2_SMEM 98304
#define NT_ (T_ / 64)

__global__ __launch_bounds__(256, 2) void attn2()
{
    extern __shared__ char sm2[];
    uint32_t sb = smem_u32(sm2);
    const int tid = threadIdx.x, lane = tid & 31, w = tid >> 5;
    const int g = lane >> 2, q4 = lane & 3;
    const int lm = lane & 15, lhi = lane >> 4;
    const int h = blockIdx.x, q0 = blockIdx.y * 128;
    const uint32_t ONES2 = 0x3C003C00u;   // half2(1,1)

    const size_t vbase = (size_t)h * HD_ * T_;

    // ---- prologue: Q + K(0) + V(0) ----
    #pragma unroll
    for (int i = 0; i < 8; i++) {
        int ch = tid + i * 256;
        int r = ch >> 4, c = ch & 15;
        CP_ASYNC16(sb + AQ_OFF2 + r * 256 + ((c ^ (r & 7)) << 4),
                   g_qfh + (size_t)(q0 + r) * D_ + h * HD_ + c * 8);
    }
    #pragma unroll
    for (int i = 0; i < 4; i++) {
        int ch = tid + i * 256;
        int r = ch >> 4, c = ch & 15;
        CP_ASYNC16(sb + AK2(0) + r * 256 + ((c ^ (r & 7)) << 4),
                   g_kfh + (size_t)r * D_ + h * HD_ + c * 8);
    }
    #pragma unroll
    for (int i = 0; i < 4; i++) {
        int ch = tid + i * 256;
        int r = ch >> 3, c = ch & 7;
        uint32_t so = r * 128 + ((c ^ (r & 7)) << 4);
        CP_ASYNC16(sb + AV2(0) + so, g_vft + vbase + (size_t)r * T_ + c * 8);
    }
    CP_COMMIT();

    float o[16][4] = {};
    float lsum[4] = {};     // [0]: row sum (row0), [2]: row sum (row0+8)
    const int row0 = q0 + w * 16 + g;

    CP_WAIT0();
    __syncthreads();

    for (int ti = 0; ti < NT_; ti++) {
        const int kt = ti * 64;

        // ---- issue K(ti+1), V(ti+1) (stage last read in tile ti-1) ----
        if (ti + 1 < NT_) {
            const int kn = kt + 64;
            const int sn = (ti + 1) & 1;
            #pragma unroll
            for (int i = 0; i < 4; i++) {
                int ch = tid + i * 256;
                int r = ch >> 4, c = ch & 15;
                CP_ASYNC16(sb + AK2(sn) + r * 256 + ((c ^ (r & 7)) << 4),
                           g_kfh + (size_t)(kn + r) * D_ + h * HD_ + c * 8);
            }
            #pragma unroll
            for (int i = 0; i < 4; i++) {
                int ch = tid + i * 256;
                int r = ch >> 3, c = ch & 7;
                uint32_t so = r * 128 + ((c ^ (r & 7)) << 4);
                CP_ASYNC16(sb + AV2(sn) + so,
                           g_vft + vbase + (size_t)r * T_ + kn + c * 8);
            }
            CP_COMMIT();
        }

        const uint32_t k_base = sb + AK2(ti & 1);
        const uint32_t v_base = sb + AV2(ti & 1);

        // ---- two 32-key halves (ROLLED loop): S(h) then P(h) ----
        #pragma unroll 1
        for (int hh = 0; hh < 2; hh++) {
            // mask for this half (8 regs, pre-scaled by log2e, fp16x2)
            uint32_t mfr[8];
            {
                const __half* mb0 =
                    g_maskh + (size_t)row0 * T_ + kt + hh * 32 + q4 * 2;
                #pragma unroll
                for (int nf = 0; nf < 4; nf++) {
                    mfr[nf]     = *(const uint32_t*)(mb0 + nf * 8);
                    mfr[4 + nf] = *(const uint32_t*)(mb0 + 8 * T_ + nf * 8);
                }
            }

            // S = Q K^T for keys [kt+hh*32, kt+hh*32+32)
            float s[4][4] = {};
            #pragma unroll
            for (int ks = 0; ks < 8; ks++) {
                int cb = ks * 2 + lhi;
                uint32_t aq[4];
                {
                    int r = w * 16 + lm;
                    ldsm4(aq, sb + AQ_OFF2 + r * 256 + ((cb ^ (r & 7)) << 4));
                }
                #pragma unroll
                for (int n2 = 0; n2 < 2; n2++) {
                    uint32_t kf[4];
                    int r = hh * 32 + n2 * 16 + lm;
                    ldsm4(kf, k_base + r * 256 + ((cb ^ (r & 7)) << 4));
                    mma16816h(s[2 * n2],     aq, kf[0], kf[2]);
                    mma16816h(s[2 * n2 + 1], aq, kf[1], kf[3]);
                }
            }

            // P = 2^(S + mask); row sums via ones-MMA; O += P V
            #pragma unroll
            for (int j = 0; j < 2; j++) {
                uint32_t ph[4];
                #pragma unroll
                for (int u = 0; u < 2; u++) {
                    int idx = 2 * j + u;
                    __half2 hab = __floats2half2_rn(s[idx][0], s[idx][1]);
                    __half2 hcd = __floats2half2_rn(s[idx][2], s[idx][3]);
                    hab = __hadd2(hab, *reinterpret_cast<__half2*>(&mfr[idx]));
                    hcd = __hadd2(hcd, *reinterpret_cast<__half2*>(&mfr[4 + idx]));
                    ph[2 * u]     = ex2h2(*reinterpret_cast<unsigned*>(&hab));
                    ph[2 * u + 1] = ex2h2(*reinterpret_cast<unsigned*>(&hcd));
                }
                mma16816h(lsum, ph, ONES2, ONES2);

                int cb = (hh * 2 + j) * 2 + lhi;
                #pragma unroll
                for (int n2 = 0; n2 < 8; n2++) {
                    uint32_t vh[4];
                    int r = n2 * 16 + lm;
                    ldsm4(vh, v_base + r * 128 + ((cb ^ (r & 7)) << 4));
                    mma16816h(o[2 * n2],     ph, vh[0], vh[2]);
                    mma16816h(o[2 * n2 + 1], ph, vh[1], vh[3]);
                }
            }
        }

        // ---- single barrier per tile ----
        if (ti + 1 < NT_) {
            CP_WAIT0();
            __syncthreads();
        }
    }

    // ---- epilogue: normalize by ones-MMA row sums + bf16 hi/lo split ----
    float inv0 = 1.f / lsum[0], inv1 = 1.f / lsum[2];
    size_t base0 = (size_t)row0 * D_ + h * HD_ + q4 * 2;
    size_t base1 = base0 + (size_t)8 * D_;
    #pragma unroll
    for (int nf = 0; nf < 16; nf++) {
        float a = o[nf][0] * inv0, b = o[nf][1] * inv0;
        __nv_bfloat162 hb = __floats2bfloat162_rn(a, b);
        __nv_bfloat162 lb = __floats2bfloat162_rn(
            a - __low2float(hb), b - __high2float(hb));
        *(uint32_t*)(g_aoh + base0 + nf * 8) = *reinterpret_cast<unsigned*>(&hb);
        *(uint32_t*)(g_aol + base0 + nf * 8) = *reinterpret_cast<unsigned*>(&lb);
        float cme = o[nf][2] * inv1, d = o[nf][3] * inv1;
        __nv_bfloat162 hb1 = __floats2bfloat162_rn(cme, d);
        __nv_bfloat162 lb1 = __floats2bfloat162_rn(
            cme - __low2float(hb1), d - __high2float(hb1));
        *(uint32_t*)(g_aoh + base1 + nf * 8) = *reinterpret_cast<unsigned*>(&hb1);
        *(uint32_t*)(g_aol + base1 + nf * 8) = *reinterpret_cast<unsigned*>(&lb1);
    }
}

// =================================================================
// Launch
// =================================================================
extern "C" void kernel_launch(void* const* d_in, const int* in_sizes, int n_in,
                              void* d_out, int out_size)
{
    const float* x    = (const float*)d_in[0];
    const float* mask = (const float*)d_in[1];
    const float* Wqkv = (const float*)d_in[2];
    const float* Wout = (const float*)d_in[3];
    float* out = (float*)d_out;

    float* qkv;
    __nv_bfloat16 *xh, *xl, *wqh, *wql, *woh, *wol, *aoh, *aol;
    cudaGetSymbolAddress((void**)&qkv, g_qkv);
    cudaGetSymbolAddress((void**)&xh,  g_xh);
    cudaGetSymbolAddress((void**)&xl,  g_xl);
    cudaGetSymbolAddress((void**)&wqh, g_wqh);
    cudaGetSymbolAddress((void**)&wql, g_wql);
    cudaGetSymbolAddress((void**)&woh, g_woh);
    cudaGetSymbolAddress((void**)&wol, g_wol);
    cudaGetSymbolAddress((void**)&aoh, g_aoh);
    cudaGetSymbolAddress((void**)&aol, g_aol);

    cudaFuncSetAttribute(gemm_split,
                         cudaFuncAttributeMaxDynamicSharedMemorySize, GEMM_SMEM);
    cudaFuncSetAttribute(attn2,
                         cudaFuncAttributeMaxDynamicSharedMemorySize, ATTN2_SMEM);

    // 1) split x / weights; mask*log2e -> fp16
    split_hl<<<(T_ * D_ / 4) / 256, 256>>>((const float4*)x, (uint2*)xh, (uint2*)xl);
    tsplit<<<dim3(TD3 / 32, D_ / 32), dim3(32, 8)>>>(Wqkv, wqh, wql, D_, TD3);
    tsplit<<<dim3(D_ / 32,  D_ / 32), dim3(32, 8)>>>(Wout, woh, wol, D_, D_);
    mask2bf<<<(T_ * (size_t)T_ / 4) / 256, 256>>>((const float4*)mask);

    // 2) qkv = x @ W_qkv
    gemm_split<<<dim3(TD3 / BN, T_ / BM), 256, GEMM_SMEM>>>(
        xh, xl, wqh, wql, qkv, T_, TD3, D_);

    // 3) normalize q (scale*log2e folded), k -> fp16; transpose V -> fp16
    l2norm_qk<<<(T_ * H_ * 2) / 8, 256>>>();
    vtsplit<<<dim3(T_ / 32, HD_ / 32, H_), dim3(32, 8)>>>();

    // 4) fp16 flash attention (register-diet half-tile schedule, rolled)
    attn2<<<dim3(H_, T_ / 128), 256, ATTN2_SMEM>>>();

    // 5) out = ao @ W_out
    gemm_split<<<dim3(D_ / BN, T_ / BM), 256, GEMM_SMEM>>>(
        aoh, aol, woh, wol, out, T_, D_, D_);
}